// round 1
// baseline (speedup 1.0000x reference)
#include <cuda_runtime.h>
#include <cuda_fp16.h>
#include <stdint.h>

#define B_SZ     4096
#define D0       1024
#define D1       8192
#define D2       8192
#define D3       10240
#define NNEUR    (D1 + D2 + D3)     // 26624
#define KCLS     10
#define GRP      (D3 / KCLS)        // 1024
#define TAU      30.0f
#define ROWS     6                  // batch rows per CTA
#define R2       (ROWS / 2)         // half2 slots per neuron
#define NTHREADS 512
#define NWARP    (NTHREADS / 32)    // 16

// -------- precomputed per-neuron metadata (device globals, no allocs) --------
__device__ uint32_t g_idx[NNEUR];   // ia | (ib<<16)
__device__ uint32_t g_c01[NNEUR];   // half2(c0,c1)
__device__ uint32_t g_c23[NNEUR];   // half2(c2,c3)

__constant__ float OPC[16][4] = {
    {0.f, 0.f, 0.f, 0.f}, {0.f, 0.f, 0.f, 1.f}, {0.f, 1.f, 0.f, -1.f}, {0.f, 1.f, 0.f, 0.f},
    {0.f, 0.f, 1.f, -1.f}, {0.f, 0.f, 1.f, 0.f}, {0.f, 1.f, 1.f, -2.f}, {0.f, 1.f, 1.f, -1.f},
    {1.f, -1.f, -1.f, 1.f}, {1.f, -1.f, -1.f, 2.f}, {1.f, 0.f, -1.f, 0.f}, {1.f, 0.f, -1.f, 1.f},
    {1.f, -1.f, 0.f, 0.f}, {1.f, -1.f, 0.f, 1.f}, {1.f, 0.f, 0.f, -1.f}, {1.f, 0.f, 0.f, 0.f}};

__global__ void precompute_kernel(
    const float* __restrict__ w1, const float* __restrict__ w2, const float* __restrict__ w3,
    const int* __restrict__ ia1, const int* __restrict__ ib1,
    const int* __restrict__ ia2, const int* __restrict__ ib2,
    const int* __restrict__ ia3, const int* __restrict__ ib3)
{
    int j = blockIdx.x * blockDim.x + threadIdx.x;
    if (j >= NNEUR) return;
    const float* w; int ia, ib;
    if (j < D1)            { w = w1 + (size_t)j * 16;               ia = ia1[j];            ib = ib1[j]; }
    else if (j < D1 + D2)  { int k = j - D1;      w = w2 + (size_t)k * 16; ia = ia2[k]; ib = ib2[k]; }
    else                   { int k = j - D1 - D2; w = w3 + (size_t)k * 16; ia = ia3[k]; ib = ib3[k]; }

    float v[16]; float m = -3.4e38f;
#pragma unroll
    for (int i = 0; i < 16; i++) { v[i] = w[i]; m = fmaxf(m, v[i]); }
    float s = 0.f;
#pragma unroll
    for (int i = 0; i < 16; i++) { v[i] = expf(v[i] - m); s += v[i]; }
    float inv = 1.f / s;
    float c0 = 0.f, c1 = 0.f, c2 = 0.f, c3 = 0.f;
#pragma unroll
    for (int i = 0; i < 16; i++) {
        float p = v[i] * inv;
        c0 = fmaf(p, OPC[i][0], c0);
        c1 = fmaf(p, OPC[i][1], c1);
        c2 = fmaf(p, OPC[i][2], c2);
        c3 = fmaf(p, OPC[i][3], c3);
    }
    g_idx[j] = (uint32_t)ia | ((uint32_t)ib << 16);
    __half2 h01 = __floats2half2_rn(c0, c1);
    __half2 h23 = __floats2half2_rn(c2, c3);
    g_c01[j] = *reinterpret_cast<uint32_t*>(&h01);
    g_c23[j] = *reinterpret_cast<uint32_t*>(&h23);
}

// -------- main kernel: whole network resident in shared memory --------------

__device__ __forceinline__ void run_layer(const __half2* __restrict__ src,
                                          __half2* __restrict__ dst,
                                          int metaBase, int D, int tid)
{
    for (int j = tid; j < D; j += NTHREADS) {
        int mj = metaBase + j;
        uint32_t pk  = __ldg(&g_idx[mj]);
        uint32_t u01 = __ldg(&g_c01[mj]);
        uint32_t u23 = __ldg(&g_c23[mj]);
        float2 c01 = __half22float2(*reinterpret_cast<__half2*>(&u01));
        float2 c23 = __half22float2(*reinterpret_cast<__half2*>(&u23));
        int ia = (int)(pk & 0xffffu) * R2;
        int ib = (int)(pk >> 16) * R2;
#pragma unroll
        for (int r = 0; r < R2; r++) {
            float2 a = __half22float2(src[ia + r]);
            float2 b = __half22float2(src[ib + r]);
            // c0 + c1*a + c2*b + c3*a*b = (c1 + c3*b)*a + (c0 + c2*b)
            float o0 = fmaf(fmaf(c23.y, b.x, c01.y), a.x, fmaf(c23.x, b.x, c01.x));
            float o1 = fmaf(fmaf(c23.y, b.y, c01.y), a.y, fmaf(c23.x, b.y, c01.x));
            dst[j * R2 + r] = __floats2half2_rn(o0, o1);
        }
    }
}

__global__ void __launch_bounds__(NTHREADS, 1)
diff_logic_main(const float* __restrict__ x, float* __restrict__ out)
{
    extern __shared__ __align__(16) uint32_t smem_raw[];
    __half2* xs = reinterpret_cast<__half2*>(smem_raw);   // D0*R2 half2
    __half2* h1 = xs + D0 * R2;                           // D1*R2 half2
    __half2* h2 = h1 + D1 * R2;                           // D2*R2 half2
    float* wacc = reinterpret_cast<float*>(h2 + D2 * R2); // KCLS*NWARP*ROWS floats

    const int tid  = threadIdx.x;
    const int row0 = blockIdx.x * ROWS;

    // Load 6 batch rows of x, interleaved fp16: half index = col*ROWS + r
    __half* xsh = reinterpret_cast<__half*>(xs);
    for (int i = tid; i < D0 * ROWS; i += NTHREADS) {
        int r   = i / D0;
        int col = i - r * D0;
        int row = row0 + r; if (row >= B_SZ) row = B_SZ - 1;   // clamp (dup work, guarded stores)
        xsh[col * ROWS + r] = __float2half_rn(x[(size_t)row * D0 + col]);
    }
    __syncthreads();

    run_layer(xs, h1, 0, D1, tid);
    __syncthreads();
    run_layer(h1, h2, D1, D2, tid);
    __syncthreads();

    // Layer 3 fused with group-sum: never materialized.
    const int lane = tid & 31;
    const int warp = tid >> 5;

    for (int g = 0; g < KCLS; g++) {
        float acc[ROWS];
#pragma unroll
        for (int r = 0; r < ROWS; r++) acc[r] = 0.f;
#pragma unroll
        for (int it = 0; it < GRP / NTHREADS; it++) {   // 1024/512 = 2
            int j  = g * GRP + it * NTHREADS + tid;
            int mj = D1 + D2 + j;
            uint32_t pk  = __ldg(&g_idx[mj]);
            uint32_t u01 = __ldg(&g_c01[mj]);
            uint32_t u23 = __ldg(&g_c23[mj]);
            float2 c01 = __half22float2(*reinterpret_cast<__half2*>(&u01));
            float2 c23 = __half22float2(*reinterpret_cast<__half2*>(&u23));
            int ia = (int)(pk & 0xffffu) * R2;
            int ib = (int)(pk >> 16) * R2;
#pragma unroll
            for (int r = 0; r < R2; r++) {
                float2 a = __half22float2(h2[ia + r]);
                float2 b = __half22float2(h2[ib + r]);
                acc[2 * r + 0] += fmaf(fmaf(c23.y, b.x, c01.y), a.x, fmaf(c23.x, b.x, c01.x));
                acc[2 * r + 1] += fmaf(fmaf(c23.y, b.y, c01.y), a.y, fmaf(c23.x, b.y, c01.x));
            }
        }
        // Deterministic reduction: warp shuffle -> per-warp partials in smem.
#pragma unroll
        for (int r = 0; r < ROWS; r++) {
#pragma unroll
            for (int off = 16; off > 0; off >>= 1)
                acc[r] += __shfl_down_sync(0xffffffffu, acc[r], off);
        }
        if (lane == 0) {
#pragma unroll
            for (int r = 0; r < ROWS; r++)
                wacc[(g * NWARP + warp) * ROWS + r] = acc[r];
        }
    }
    __syncthreads();

    if (tid < KCLS * ROWS) {
        int g = tid / ROWS;
        int r = tid - g * ROWS;
        int row = row0 + r;
        if (row < B_SZ) {
            float s = 0.f;
#pragma unroll
            for (int w = 0; w < NWARP; w++)
                s += wacc[(g * NWARP + w) * ROWS + r];
            out[(size_t)row * KCLS + g] = s * (1.f / TAU);
        }
    }
}

// -----------------------------------------------------------------------------

extern "C" void kernel_launch(void* const* d_in, const int* in_sizes, int n_in,
                              void* d_out, int out_size)
{
    (void)in_sizes; (void)n_in; (void)out_size;
    const float* x  = (const float*)d_in[0];
    const float* w1 = (const float*)d_in[1];
    const float* w2 = (const float*)d_in[2];
    const float* w3 = (const float*)d_in[3];
    const int* ia1 = (const int*)d_in[4];
    const int* ib1 = (const int*)d_in[5];
    const int* ia2 = (const int*)d_in[6];
    const int* ib2 = (const int*)d_in[7];
    const int* ia3 = (const int*)d_in[8];
    const int* ib3 = (const int*)d_in[9];
    float* out = (float*)d_out;

    precompute_kernel<<<(NNEUR + 255) / 256, 256>>>(w1, w2, w3, ia1, ib1, ia2, ib2, ia3, ib3);

    size_t smem = (size_t)(D0 * R2 + D1 * R2 + D2 * R2) * sizeof(__half2)
                + (size_t)(KCLS * NWARP * ROWS) * sizeof(float);   // 212,736 B
    cudaFuncSetAttribute(diff_logic_main, cudaFuncAttributeMaxDynamicSharedMemorySize, (int)smem);

    int grid = (B_SZ + ROWS - 1) / ROWS;   // 683
    diff_logic_main<<<grid, NTHREADS, smem>>>(x, out);
}

// round 2
// speedup vs baseline: 1.1080x; 1.1080x over previous
#include <cuda_runtime.h>
#include <cuda_fp16.h>
#include <stdint.h>

#define B_SZ     4096
#define D0       1024
#define D1       8192
#define D2       8192
#define D3       10240
#define NNEUR    (D1 + D2 + D3)     // 26624
#define KCLS     10
#define GRP      (D3 / KCLS)        // 1024
#define TAU      30.0f
#define ROWS     6                  // batch rows per CTA
#define R2       (ROWS / 2)         // half2 slots per neuron
#define NTHREADS 1024
#define NWARP    (NTHREADS / 32)    // 32

// -------- precomputed per-neuron metadata (device globals, no allocs) --------
__device__ uint32_t g_idx[NNEUR];   // ia | (ib<<16)
__device__ uint32_t g_c01[NNEUR];   // half2(c0,c1)
__device__ uint32_t g_c23[NNEUR];   // half2(c2,c3)

__constant__ float OPC[16][4] = {
    {0.f, 0.f, 0.f, 0.f}, {0.f, 0.f, 0.f, 1.f}, {0.f, 1.f, 0.f, -1.f}, {0.f, 1.f, 0.f, 0.f},
    {0.f, 0.f, 1.f, -1.f}, {0.f, 0.f, 1.f, 0.f}, {0.f, 1.f, 1.f, -2.f}, {0.f, 1.f, 1.f, -1.f},
    {1.f, -1.f, -1.f, 1.f}, {1.f, -1.f, -1.f, 2.f}, {1.f, 0.f, -1.f, 0.f}, {1.f, 0.f, -1.f, 1.f},
    {1.f, -1.f, 0.f, 0.f}, {1.f, -1.f, 0.f, 1.f}, {1.f, 0.f, 0.f, -1.f}, {1.f, 0.f, 0.f, 0.f}};

__global__ void precompute_kernel(
    const float* __restrict__ w1, const float* __restrict__ w2, const float* __restrict__ w3,
    const int* __restrict__ ia1, const int* __restrict__ ib1,
    const int* __restrict__ ia2, const int* __restrict__ ib2,
    const int* __restrict__ ia3, const int* __restrict__ ib3)
{
    int j = blockIdx.x * blockDim.x + threadIdx.x;
    if (j >= NNEUR) return;
    const float* w; int ia, ib;
    if (j < D1)            { w = w1 + (size_t)j * 16;               ia = ia1[j];            ib = ib1[j]; }
    else if (j < D1 + D2)  { int k = j - D1;      w = w2 + (size_t)k * 16; ia = ia2[k]; ib = ib2[k]; }
    else                   { int k = j - D1 - D2; w = w3 + (size_t)k * 16; ia = ia3[k]; ib = ib3[k]; }

    float v[16]; float m = -3.4e38f;
#pragma unroll
    for (int i = 0; i < 16; i++) { v[i] = w[i]; m = fmaxf(m, v[i]); }
    float s = 0.f;
#pragma unroll
    for (int i = 0; i < 16; i++) { v[i] = expf(v[i] - m); s += v[i]; }
    float inv = 1.f / s;
    float c0 = 0.f, c1 = 0.f, c2 = 0.f, c3 = 0.f;
#pragma unroll
    for (int i = 0; i < 16; i++) {
        float p = v[i] * inv;
        c0 = fmaf(p, OPC[i][0], c0);
        c1 = fmaf(p, OPC[i][1], c1);
        c2 = fmaf(p, OPC[i][2], c2);
        c3 = fmaf(p, OPC[i][3], c3);
    }
    g_idx[j] = (uint32_t)ia | ((uint32_t)ib << 16);
    __half2 h01 = __floats2half2_rn(c0, c1);
    __half2 h23 = __floats2half2_rn(c2, c3);
    g_c01[j] = *reinterpret_cast<uint32_t*>(&h01);
    g_c23[j] = *reinterpret_cast<uint32_t*>(&h23);
}

// -------- main kernel: whole network resident in shared memory --------------

struct NeuronIn {
    uint32_t pk, u01, u23;
    __half2 a[R2], b[R2];
};

__device__ __forceinline__ void fetch_neuron(const __half2* __restrict__ src,
                                             int mj, NeuronIn& n)
{
    n.pk  = __ldg(&g_idx[mj]);
    n.u01 = __ldg(&g_c01[mj]);
    n.u23 = __ldg(&g_c23[mj]);
    int ia = (int)(n.pk & 0xffffu) * R2;
    int ib = (int)(n.pk >> 16) * R2;
#pragma unroll
    for (int r = 0; r < R2; r++) { n.a[r] = src[ia + r]; n.b[r] = src[ib + r]; }
}

__device__ __forceinline__ void compute_neuron(const NeuronIn& n, __half2* __restrict__ dst, int j)
{
    float2 c01 = __half22float2(*reinterpret_cast<const __half2*>(&n.u01));
    float2 c23 = __half22float2(*reinterpret_cast<const __half2*>(&n.u23));
#pragma unroll
    for (int r = 0; r < R2; r++) {
        float2 a = __half22float2(n.a[r]);
        float2 b = __half22float2(n.b[r]);
        float o0 = fmaf(fmaf(c23.y, b.x, c01.y), a.x, fmaf(c23.x, b.x, c01.x));
        float o1 = fmaf(fmaf(c23.y, b.y, c01.y), a.y, fmaf(c23.x, b.y, c01.x));
        dst[j * R2 + r] = __floats2half2_rn(o0, o1);
    }
}

// D is a multiple of 2*NTHREADS for all layers (8192/1024=8), so the
// 2-deep pipeline needs no tail guards.
__device__ __forceinline__ void run_layer(const __half2* __restrict__ src,
                                          __half2* __restrict__ dst,
                                          int metaBase, int D, int tid)
{
    const int iters = D / NTHREADS;   // even
    NeuronIn cur, nxt;
    int j = tid;
    fetch_neuron(src, metaBase + j, cur);
#pragma unroll 2
    for (int it = 0; it < iters - 1; it++) {
        fetch_neuron(src, metaBase + j + NTHREADS, nxt);
        compute_neuron(cur, dst, j);
        cur = nxt;
        j += NTHREADS;
    }
    compute_neuron(cur, dst, j);
}

__global__ void __launch_bounds__(NTHREADS, 1)
diff_logic_main(const float* __restrict__ x, float* __restrict__ out)
{
    extern __shared__ __align__(16) uint32_t smem_raw[];
    __half2* xs = reinterpret_cast<__half2*>(smem_raw);   // D0*R2 half2
    __half2* h1 = xs + D0 * R2;                           // D1*R2 half2
    __half2* h2 = h1 + D1 * R2;                           // D2*R2 half2
    float* wacc = reinterpret_cast<float*>(h2 + D2 * R2); // KCLS*NWARP*ROWS floats

    const int tid  = threadIdx.x;
    const int row0 = blockIdx.x * ROWS;

    // Load 6 batch rows of x (vectorized float4), interleave fp16 as col*ROWS + r
    __half* xsh = reinterpret_cast<__half*>(xs);
    {
        const int total = D0 * ROWS / 4;   // 1536 float4 loads
        for (int i = tid; i < total; i += NTHREADS) {
            int r    = i / (D0 / 4);
            int c4   = i - r * (D0 / 4);
            int row  = row0 + r; if (row >= B_SZ) row = B_SZ - 1;  // clamp; out stores guarded
            float4 v = *reinterpret_cast<const float4*>(&x[(size_t)row * D0 + c4 * 4]);
            int col  = c4 * 4;
            xsh[(col + 0) * ROWS + r] = __float2half_rn(v.x);
            xsh[(col + 1) * ROWS + r] = __float2half_rn(v.y);
            xsh[(col + 2) * ROWS + r] = __float2half_rn(v.z);
            xsh[(col + 3) * ROWS + r] = __float2half_rn(v.w);
        }
    }
    __syncthreads();

    run_layer(xs, h1, 0, D1, tid);
    __syncthreads();
    run_layer(h1, h2, D1, D2, tid);
    __syncthreads();

    // Layer 3 fused with group-sum: never materialized.
    const int lane = tid & 31;
    const int warp = tid >> 5;

    for (int g = 0; g < KCLS; g++) {
        float acc[ROWS];
#pragma unroll
        for (int r = 0; r < ROWS; r++) acc[r] = 0.f;
        {   // GRP / NTHREADS == 1
            int j  = g * GRP + tid;
            int mj = D1 + D2 + j;
            uint32_t pk  = __ldg(&g_idx[mj]);
            uint32_t u01 = __ldg(&g_c01[mj]);
            uint32_t u23 = __ldg(&g_c23[mj]);
            float2 c01 = __half22float2(*reinterpret_cast<__half2*>(&u01));
            float2 c23 = __half22float2(*reinterpret_cast<__half2*>(&u23));
            int ia = (int)(pk & 0xffffu) * R2;
            int ib = (int)(pk >> 16) * R2;
#pragma unroll
            for (int r = 0; r < R2; r++) {
                float2 a = __half22float2(h2[ia + r]);
                float2 b = __half22float2(h2[ib + r]);
                acc[2 * r + 0] += fmaf(fmaf(c23.y, b.x, c01.y), a.x, fmaf(c23.x, b.x, c01.x));
                acc[2 * r + 1] += fmaf(fmaf(c23.y, b.y, c01.y), a.y, fmaf(c23.x, b.y, c01.x));
            }
        }
        // Deterministic reduction: warp shuffle -> per-warp partials in smem.
#pragma unroll
        for (int r = 0; r < ROWS; r++) {
#pragma unroll
            for (int off = 16; off > 0; off >>= 1)
                acc[r] += __shfl_down_sync(0xffffffffu, acc[r], off);
        }
        if (lane == 0) {
#pragma unroll
            for (int r = 0; r < ROWS; r++)
                wacc[(g * NWARP + warp) * ROWS + r] = acc[r];
        }
    }
    __syncthreads();

    if (tid < KCLS * ROWS) {
        int g = tid / ROWS;
        int r = tid - g * ROWS;
        int row = row0 + r;
        if (row < B_SZ) {
            float s = 0.f;
#pragma unroll
            for (int w = 0; w < NWARP; w++)
                s += wacc[(g * NWARP + w) * ROWS + r];
            out[(size_t)row * KCLS + g] = s * (1.f / TAU);
        }
    }
}

// -----------------------------------------------------------------------------

extern "C" void kernel_launch(void* const* d_in, const int* in_sizes, int n_in,
                              void* d_out, int out_size)
{
    (void)in_sizes; (void)n_in; (void)out_size;
    const float* x  = (const float*)d_in[0];
    const float* w1 = (const float*)d_in[1];
    const float* w2 = (const float*)d_in[2];
    const float* w3 = (const float*)d_in[3];
    const int* ia1 = (const int*)d_in[4];
    const int* ib1 = (const int*)d_in[5];
    const int* ia2 = (const int*)d_in[6];
    const int* ib2 = (const int*)d_in[7];
    const int* ia3 = (const int*)d_in[8];
    const int* ib3 = (const int*)d_in[9];
    float* out = (float*)d_out;

    precompute_kernel<<<(NNEUR + 255) / 256, 256>>>(w1, w2, w3, ia1, ib1, ia2, ib2, ia3, ib3);

    size_t smem = (size_t)(D0 * R2 + D1 * R2 + D2 * R2) * sizeof(__half2)
                + (size_t)(KCLS * NWARP * ROWS) * sizeof(float);   // 216,576 B
    cudaFuncSetAttribute(diff_logic_main, cudaFuncAttributeMaxDynamicSharedMemorySize, (int)smem);

    int grid = (B_SZ + ROWS - 1) / ROWS;   // 683
    diff_logic_main<<<grid, NTHREADS, smem>>>(x, out);
}

// round 3
// speedup vs baseline: 1.1733x; 1.0589x over previous
#include <cuda_runtime.h>
#include <cuda_fp16.h>
#include <stdint.h>

#define B_SZ     4096
#define D0       1024
#define D1       8192
#define D2       8192
#define D3       10240
#define NNEUR    (D1 + D2 + D3)     // 26624
#define KCLS     10
#define GRP      (D3 / KCLS)        // 1024
#define TAU      30.0f
#define ROWS     4                  // batch rows per CTA (4096/4 = 1024 CTAs, exact)
#define R2       (ROWS / 2)         // 2 half2 = one uint2 (8B) per neuron slot
#define NTHREADS 1024
#define NWARP    (NTHREADS / 32)    // 32

// -------- precomputed per-neuron metadata (device globals, no allocs) --------
__device__ uint32_t g_idx[NNEUR];   // ia | (ib<<16)
__device__ uint32_t g_c01[NNEUR];   // half2(c0,c1)
__device__ uint32_t g_c23[NNEUR];   // half2(c2,c3)

__constant__ float OPC[16][4] = {
    {0.f, 0.f, 0.f, 0.f}, {0.f, 0.f, 0.f, 1.f}, {0.f, 1.f, 0.f, -1.f}, {0.f, 1.f, 0.f, 0.f},
    {0.f, 0.f, 1.f, -1.f}, {0.f, 0.f, 1.f, 0.f}, {0.f, 1.f, 1.f, -2.f}, {0.f, 1.f, 1.f, -1.f},
    {1.f, -1.f, -1.f, 1.f}, {1.f, -1.f, -1.f, 2.f}, {1.f, 0.f, -1.f, 0.f}, {1.f, 0.f, -1.f, 1.f},
    {1.f, -1.f, 0.f, 0.f}, {1.f, -1.f, 0.f, 1.f}, {1.f, 0.f, 0.f, -1.f}, {1.f, 0.f, 0.f, 0.f}};

__global__ void precompute_kernel(
    const float* __restrict__ w1, const float* __restrict__ w2, const float* __restrict__ w3,
    const int* __restrict__ ia1, const int* __restrict__ ib1,
    const int* __restrict__ ia2, const int* __restrict__ ib2,
    const int* __restrict__ ia3, const int* __restrict__ ib3)
{
    int j = blockIdx.x * blockDim.x + threadIdx.x;
    if (j >= NNEUR) return;
    const float* w; int ia, ib;
    if (j < D1)            { w = w1 + (size_t)j * 16;               ia = ia1[j];            ib = ib1[j]; }
    else if (j < D1 + D2)  { int k = j - D1;      w = w2 + (size_t)k * 16; ia = ia2[k]; ib = ib2[k]; }
    else                   { int k = j - D1 - D2; w = w3 + (size_t)k * 16; ia = ia3[k]; ib = ib3[k]; }

    float v[16]; float m = -3.4e38f;
#pragma unroll
    for (int i = 0; i < 16; i++) { v[i] = w[i]; m = fmaxf(m, v[i]); }
    float s = 0.f;
#pragma unroll
    for (int i = 0; i < 16; i++) { v[i] = expf(v[i] - m); s += v[i]; }
    float inv = 1.f / s;
    float c0 = 0.f, c1 = 0.f, c2 = 0.f, c3 = 0.f;
#pragma unroll
    for (int i = 0; i < 16; i++) {
        float p = v[i] * inv;
        c0 = fmaf(p, OPC[i][0], c0);
        c1 = fmaf(p, OPC[i][1], c1);
        c2 = fmaf(p, OPC[i][2], c2);
        c3 = fmaf(p, OPC[i][3], c3);
    }
    g_idx[j] = (uint32_t)ia | ((uint32_t)ib << 16);
    __half2 h01 = __floats2half2_rn(c0, c1);
    __half2 h23 = __floats2half2_rn(c2, c3);
    g_c01[j] = *reinterpret_cast<uint32_t*>(&h01);
    g_c23[j] = *reinterpret_cast<uint32_t*>(&h23);
}

// -------- main kernel: whole network resident in shared memory --------------
// One smem slot per neuron = uint2 (4 batch rows as 2x half2). All gathers are
// single LDS.64; all stores single conflict-free STS.64.

struct NeuronIn {
    uint32_t pk, u01, u23;
    uint2 a, b;
};

__device__ __forceinline__ void fetch_neuron(const uint2* __restrict__ src,
                                             int mj, NeuronIn& n)
{
    n.pk  = __ldg(&g_idx[mj]);
    n.u01 = __ldg(&g_c01[mj]);
    n.u23 = __ldg(&g_c23[mj]);
    n.a = src[n.pk & 0xffffu];
    n.b = src[n.pk >> 16];
}

__device__ __forceinline__ uint2 neuron_math(const NeuronIn& n)
{
    float2 c01 = __half22float2(*reinterpret_cast<const __half2*>(&n.u01));
    float2 c23 = __half22float2(*reinterpret_cast<const __half2*>(&n.u23));
    uint2 o;
#pragma unroll
    for (int r = 0; r < R2; r++) {
        uint32_t ua = (r == 0) ? n.a.x : n.a.y;
        uint32_t ub = (r == 0) ? n.b.x : n.b.y;
        float2 a = __half22float2(*reinterpret_cast<const __half2*>(&ua));
        float2 b = __half22float2(*reinterpret_cast<const __half2*>(&ub));
        // c0 + c1*a + c2*b + c3*a*b = (c1 + c3*b)*a + (c0 + c2*b)
        float o0 = fmaf(fmaf(c23.y, b.x, c01.y), a.x, fmaf(c23.x, b.x, c01.x));
        float o1 = fmaf(fmaf(c23.y, b.y, c01.y), a.y, fmaf(c23.x, b.y, c01.x));
        __half2 h = __floats2half2_rn(o0, o1);
        uint32_t uh = *reinterpret_cast<uint32_t*>(&h);
        if (r == 0) o.x = uh; else o.y = uh;
    }
    return o;
}

// D is a multiple of 2*NTHREADS for all layers, so the 2-deep pipeline
// needs no tail guards.
__device__ __forceinline__ void run_layer(const uint2* __restrict__ src,
                                          uint2* __restrict__ dst,
                                          int metaBase, int D, int tid)
{
    const int iters = D / NTHREADS;
    NeuronIn cur, nxt;
    int j = tid;
    fetch_neuron(src, metaBase + j, cur);
#pragma unroll 2
    for (int it = 0; it < iters - 1; it++) {
        fetch_neuron(src, metaBase + j + NTHREADS, nxt);
        dst[j] = neuron_math(cur);
        cur = nxt;
        j += NTHREADS;
    }
    dst[j] = neuron_math(cur);
}

__global__ void __launch_bounds__(NTHREADS, 1)
diff_logic_main(const float* __restrict__ x, float* __restrict__ out)
{
    extern __shared__ __align__(16) uint32_t smem_raw[];
    uint2* xs = reinterpret_cast<uint2*>(smem_raw);   // D0 slots
    uint2* h1 = xs + D0;                              // D1 slots
    uint2* h2 = h1 + D1;                              // D2 slots
    float* wacc = reinterpret_cast<float*>(h2 + D2);  // KCLS*NWARP*ROWS floats

    const int tid  = threadIdx.x;
    const int row0 = blockIdx.x * ROWS;               // exact: 4096 = 1024*4

    // Load 4 batch rows of x: each thread owns one column, reads 4 strided
    // floats (coalesced within warp per r), packs into one uint2 slot.
    {
        int col = tid;                                // D0 == NTHREADS == 1024
        float v0 = x[(size_t)(row0 + 0) * D0 + col];
        float v1 = x[(size_t)(row0 + 1) * D0 + col];
        float v2 = x[(size_t)(row0 + 2) * D0 + col];
        float v3 = x[(size_t)(row0 + 3) * D0 + col];
        __half2 p0 = __floats2half2_rn(v0, v1);
        __half2 p1 = __floats2half2_rn(v2, v3);
        uint2 slot;
        slot.x = *reinterpret_cast<uint32_t*>(&p0);
        slot.y = *reinterpret_cast<uint32_t*>(&p1);
        xs[col] = slot;
    }
    __syncthreads();

    run_layer(xs, h1, 0, D1, tid);
    __syncthreads();
    run_layer(h1, h2, D1, D2, tid);
    __syncthreads();

    // Layer 3 fused with group-sum: never materialized.
    const int lane = tid & 31;
    const int warp = tid >> 5;

    for (int g = 0; g < KCLS; g++) {
        float acc[ROWS];
#pragma unroll
        for (int r = 0; r < ROWS; r++) acc[r] = 0.f;
        {   // GRP == NTHREADS == 1024: exactly one element per thread
            int mj = D1 + D2 + g * GRP + tid;
            NeuronIn n;
            fetch_neuron(h2, mj, n);
            float2 c01 = __half22float2(*reinterpret_cast<const __half2*>(&n.u01));
            float2 c23 = __half22float2(*reinterpret_cast<const __half2*>(&n.u23));
#pragma unroll
            for (int r = 0; r < R2; r++) {
                uint32_t ua = (r == 0) ? n.a.x : n.a.y;
                uint32_t ub = (r == 0) ? n.b.x : n.b.y;
                float2 a = __half22float2(*reinterpret_cast<const __half2*>(&ua));
                float2 b = __half22float2(*reinterpret_cast<const __half2*>(&ub));
                acc[2 * r + 0] += fmaf(fmaf(c23.y, b.x, c01.y), a.x, fmaf(c23.x, b.x, c01.x));
                acc[2 * r + 1] += fmaf(fmaf(c23.y, b.y, c01.y), a.y, fmaf(c23.x, b.y, c01.x));
            }
        }
        // Deterministic reduction: warp shuffle -> per-warp partials in smem.
#pragma unroll
        for (int r = 0; r < ROWS; r++) {
#pragma unroll
            for (int off = 16; off > 0; off >>= 1)
                acc[r] += __shfl_down_sync(0xffffffffu, acc[r], off);
        }
        if (lane == 0) {
#pragma unroll
            for (int r = 0; r < ROWS; r++)
                wacc[(g * NWARP + warp) * ROWS + r] = acc[r];
        }
    }
    __syncthreads();

    if (tid < KCLS * ROWS) {
        int g = tid / ROWS;
        int r = tid - g * ROWS;
        float s = 0.f;
#pragma unroll
        for (int w = 0; w < NWARP; w++)
            s += wacc[(g * NWARP + w) * ROWS + r];
        out[(size_t)(row0 + r) * KCLS + g] = s * (1.f / TAU);
    }
}

// -----------------------------------------------------------------------------

extern "C" void kernel_launch(void* const* d_in, const int* in_sizes, int n_in,
                              void* d_out, int out_size)
{
    (void)in_sizes; (void)n_in; (void)out_size;
    const float* x  = (const float*)d_in[0];
    const float* w1 = (const float*)d_in[1];
    const float* w2 = (const float*)d_in[2];
    const float* w3 = (const float*)d_in[3];
    const int* ia1 = (const int*)d_in[4];
    const int* ib1 = (const int*)d_in[5];
    const int* ia2 = (const int*)d_in[6];
    const int* ib2 = (const int*)d_in[7];
    const int* ia3 = (const int*)d_in[8];
    const int* ib3 = (const int*)d_in[9];
    float* out = (float*)d_out;

    precompute_kernel<<<(NNEUR + 255) / 256, 256>>>(w1, w2, w3, ia1, ib1, ia2, ib2, ia3, ib3);

    size_t smem = (size_t)(D0 + D1 + D2) * sizeof(uint2)
                + (size_t)(KCLS * NWARP * ROWS) * sizeof(float);   // 144,384 B
    cudaFuncSetAttribute(diff_logic_main, cudaFuncAttributeMaxDynamicSharedMemorySize, (int)smem);

    int grid = B_SZ / ROWS;   // 1024
    diff_logic_main<<<grid, NTHREADS, smem>>>(x, out);
}